// round 2
// baseline (speedup 1.0000x reference)
#include <cuda_runtime.h>

#define NB 16          // batches per block
#define THREADS 192    // = NB * 12 exactly for phase G
#define RKSTRIDE 516   // 16*32 + 4 pad floats (bank-spread across batches)

__device__ float g_W[32 * 32];  // W[j][jp] = sum_h qw2[j,h] * kw2[jp,h]
__device__ float g_u[32];       // u[jp]    = sum_h qb2[h]   * kw2[jp,h]

__global__ void precompute_kernel(const float* __restrict__ qw2,
                                  const float* __restrict__ qb2,
                                  const float* __restrict__ kw2) {
    int t = threadIdx.x;            // 1024 threads
    int j = t >> 5, jp = t & 31;
    float s = 0.f;
    #pragma unroll
    for (int h = 0; h < 64; ++h)
        s = fmaf(qw2[j * 64 + h], kw2[jp * 64 + h], s);
    g_W[j * 32 + jp] = s;
    if (j == 0) {
        float su = 0.f;
        #pragma unroll
        for (int h = 0; h < 64; ++h)
            su = fmaf(qb2[h], kw2[jp * 64 + h], su);
        g_u[jp] = su;
    }
}

__global__ __launch_bounds__(THREADS) void nearfield_kernel(
    const float* __restrict__ rss_t,          // [B,12]
    const float* __restrict__ led_features,   // [B,16,8]
    const float* __restrict__ led_positions,  // [B,16,3]
    const float* __restrict__ prev_pos,       // [B,3]
    const int*   __restrict__ freq_mask,      // [12,16]
    const float* __restrict__ gw1, const float* __restrict__ gb1,
    const float* __restrict__ gw2, const float* __restrict__ gb2,
    const float* __restrict__ qw1, const float* __restrict__ qb1,
    const float* __restrict__ kw1, const float* __restrict__ kb1,
    const float* __restrict__ sigma,
    float* __restrict__ out_attn,             // [B,12,16]
    float* __restrict__ out_iw)               // [B,12]
{
    __shared__ __align__(16) float s_kw1[11 * 32];
    __shared__ __align__(16) float s_kb1[32];
    __shared__ __align__(16) float s_W[32 * 32];
    __shared__ __align__(16) float s_u[32];
    __shared__ __align__(16) float s_qw1[32];
    __shared__ __align__(16) float s_qb1[32];
    __shared__ float s_gw1[16], s_gb1[16], s_gw2[16];
    __shared__ float s_gb2, s_scale;
    __shared__ unsigned s_mask[12];
    __shared__ __align__(16) float s_rk[NB * RKSTRIDE];
    __shared__ float s_dist[NB * 16];

    const int tid = threadIdx.x;

    // ---- cooperative weight staging ----
    for (int i = tid; i < 352; i += THREADS) s_kw1[i] = kw1[i];
    for (int i = tid; i < 1024; i += THREADS) s_W[i] = g_W[i];
    if (tid < 32) {
        s_kb1[tid] = kb1[tid];
        s_u[tid]   = g_u[tid];
        s_qw1[tid] = qw1[tid];
        s_qb1[tid] = qb1[tid];
    }
    if (tid < 16) {
        s_gw1[tid] = gw1[tid];
        s_gb1[tid] = gb1[tid];
        s_gw2[tid] = gw2[tid];
    }
    if (tid == 0) {
        float sg = sigma[0];
        s_gb2 = gb2[0];
        s_scale = 0.5f / (sg * sg);   // 1/(2 sigma^2)
    }
    if (tid < 12) {
        unsigned m = 0;
        #pragma unroll
        for (int l = 0; l < 16; ++l)
            if (freq_mask[tid * 16 + l] != 0) m |= (1u << l);
        s_mask[tid] = m;
    }
    __syncthreads();

    const int block0 = blockIdx.x * NB;
    const float scale = s_scale;

    // ---- Phase K: rk[b][l][0..31] = relu(led_in @ kw1 + kb1), dist term ----
    for (int task = tid; task < NB * 16; task += THREADS) {
        int b = task >> 4, l = task & 15;
        int batch = block0 + b;
        float in[11];
        const float* lf = led_features + (size_t)(batch * 16 + l) * 8;
        float4 f0 = *(const float4*)(lf);
        float4 f1 = *(const float4*)(lf + 4);
        in[0] = f0.x; in[1] = f0.y; in[2] = f0.z; in[3] = f0.w;
        in[4] = f1.x; in[5] = f1.y; in[6] = f1.z; in[7] = f1.w;
        const float* lp = led_positions + (size_t)(batch * 16 + l) * 3;
        in[8] = lp[0]; in[9] = lp[1]; in[10] = lp[2];
        const float* pp = prev_pos + (size_t)batch * 3;
        float dx = pp[0] - in[8], dy = pp[1] - in[9], dz = pp[2] - in[10];
        s_dist[b * 16 + l] = (dx * dx + dy * dy + dz * dz) * scale;

        float* dst = s_rk + b * RKSTRIDE + l * 32;
        #pragma unroll
        for (int j4 = 0; j4 < 8; ++j4) {
            float4 a = *(const float4*)(s_kb1 + j4 * 4);
            #pragma unroll
            for (int d = 0; d < 11; ++d) {
                float4 w = *(const float4*)(s_kw1 + d * 32 + j4 * 4);
                a.x = fmaf(in[d], w.x, a.x);
                a.y = fmaf(in[d], w.y, a.y);
                a.z = fmaf(in[d], w.z, a.z);
                a.w = fmaf(in[d], w.w, a.w);
            }
            float4 r4;
            r4.x = fmaxf(a.x, 0.f); r4.y = fmaxf(a.y, 0.f);
            r4.z = fmaxf(a.z, 0.f); r4.w = fmaxf(a.w, 0.f);
            *(float4*)(dst + j4 * 4) = r4;
        }
    }
    __syncthreads();

    // ---- Phase G: per (batch, r): gate, Ghat = rq@W + u, scores, softmax ----
    {
        int b = tid / 12, r = tid - b * 12;    // 16*12 = 192 = THREADS
        int batch = block0 + b;
        float rss = rss_t[batch * 12 + r];

        // intensity gate MLP + hard threshold
        float gacc = s_gb2;
        #pragma unroll
        for (int k = 0; k < 16; ++k) {
            float h = fmaxf(fmaf(rss, s_gw1[k], s_gb1[k]), 0.f);
            gacc = fmaf(h, s_gw2[k], gacc);
        }
        float sig = __frcp_rn(1.f + __expf(-gacc));
        float iw = (rss > 0.5f) ? sig : 0.f;
        out_iw[batch * 12 + r] = iw;
        float x = rss * iw;

        // Ghat = u + relu(x*qw1 + qb1) @ W
        float G[32];
        #pragma unroll
        for (int j4 = 0; j4 < 8; ++j4) {
            float4 u4 = *(const float4*)(s_u + j4 * 4);
            G[j4 * 4 + 0] = u4.x; G[j4 * 4 + 1] = u4.y;
            G[j4 * 4 + 2] = u4.z; G[j4 * 4 + 3] = u4.w;
        }
        #pragma unroll
        for (int j = 0; j < 32; ++j) {
            float rq = fmaxf(fmaf(x, s_qw1[j], s_qb1[j]), 0.f);
            #pragma unroll
            for (int j4 = 0; j4 < 8; ++j4) {
                float4 w = *(const float4*)(s_W + j * 32 + j4 * 4);
                G[j4 * 4 + 0] = fmaf(rq, w.x, G[j4 * 4 + 0]);
                G[j4 * 4 + 1] = fmaf(rq, w.y, G[j4 * 4 + 1]);
                G[j4 * 4 + 2] = fmaf(rq, w.z, G[j4 * 4 + 2]);
                G[j4 * 4 + 3] = fmaf(rq, w.w, G[j4 * 4 + 3]);
            }
        }

        // scores[l] = Ghat . rk[l] - dist[l]
        float s[16];
        const float* rkb = s_rk + b * RKSTRIDE;
        #pragma unroll
        for (int l = 0; l < 16; ++l) {
            float acc = -s_dist[b * 16 + l];
            const float* rkl = rkb + l * 32;
            #pragma unroll
            for (int j4 = 0; j4 < 8; ++j4) {
                float4 v = *(const float4*)(rkl + j4 * 4);
                acc = fmaf(G[j4 * 4 + 0], v.x, acc);
                acc = fmaf(G[j4 * 4 + 1], v.y, acc);
                acc = fmaf(G[j4 * 4 + 2], v.z, acc);
                acc = fmaf(G[j4 * 4 + 3], v.w, acc);
            }
            s[l] = acc;
        }

        // masked softmax over l
        unsigned m = s_mask[r];
        if (m == 0u) {
            #pragma unroll
            for (int l = 0; l < 16; ++l) s[l] = 1.f / 16.f;
        } else {
            float mx = -3.402823466e38f;
            #pragma unroll
            for (int l = 0; l < 16; ++l)
                if (m & (1u << l)) mx = fmaxf(mx, s[l]);
            float sum = 0.f;
            #pragma unroll
            for (int l = 0; l < 16; ++l) {
                float e = (m & (1u << l)) ? __expf(s[l] - mx) : 0.f;
                s[l] = e;
                sum += e;
            }
            float inv = __frcp_rn(sum);
            #pragma unroll
            for (int l = 0; l < 16; ++l) s[l] *= inv;
        }

        float* dst = out_attn + (size_t)(batch * 12 + r) * 16;
        #pragma unroll
        for (int l4 = 0; l4 < 4; ++l4) {
            float4 o;
            o.x = s[l4 * 4 + 0]; o.y = s[l4 * 4 + 1];
            o.z = s[l4 * 4 + 2]; o.w = s[l4 * 4 + 3];
            *(float4*)(dst + l4 * 4) = o;
        }
    }
}

extern "C" void kernel_launch(void* const* d_in, const int* in_sizes, int n_in,
                              void* d_out, int out_size) {
    const float* rss_t  = (const float*)d_in[0];
    const float* led_f  = (const float*)d_in[1];
    const float* led_p  = (const float*)d_in[2];
    const float* prevp  = (const float*)d_in[3];
    const int*   fmask  = (const int*)  d_in[4];
    const float* gw1    = (const float*)d_in[5];
    const float* gb1    = (const float*)d_in[6];
    const float* gw2    = (const float*)d_in[7];
    const float* gb2    = (const float*)d_in[8];
    const float* qw1    = (const float*)d_in[9];
    const float* qb1    = (const float*)d_in[10];
    const float* qw2    = (const float*)d_in[11];
    const float* qb2    = (const float*)d_in[12];
    const float* kw1    = (const float*)d_in[13];
    const float* kb1    = (const float*)d_in[14];
    const float* kw2    = (const float*)d_in[15];
    const float* kb2    = (const float*)d_in[16];
    const float* sigma  = (const float*)d_in[17];
    (void)kb2; (void)n_in; (void)out_size;

    int B = in_sizes[0] / 12;
    float* out = (float*)d_out;
    float* out_attn = out;                       // [B,12,16]
    float* out_iw   = out + (size_t)B * 192;     // [B,12]

    precompute_kernel<<<1, 1024>>>(qw2, qb2, kw2);
    nearfield_kernel<<<B / NB, THREADS>>>(
        rss_t, led_f, led_p, prevp, fmask,
        gw1, gb1, gw2, gb2, qw1, qb1, kw1, kb1, sigma,
        out_attn, out_iw);
}

// round 5
// speedup vs baseline: 1.1862x; 1.1862x over previous
#include <cuda_runtime.h>

#define NB 16          // batches per block
#define THREADS 384    // = NB * 12 * 2 (thread-pair per (batch,r))
#define RKSTRIDE 516   // 16*32 + 4 pad floats

__device__ float g_W[32 * 32];  // W[j][jp] = sum_h qw2[j,h] * kw2[jp,h]
__device__ float g_u[32];       // u[jp]    = sum_h qb2[h]   * kw2[jp,h]

__global__ void precompute_kernel(const float* __restrict__ qw2,
                                  const float* __restrict__ qb2,
                                  const float* __restrict__ kw2) {
    int t = threadIdx.x;            // 1024 threads
    int j = t >> 5, jp = t & 31;
    float s = 0.f;
    #pragma unroll
    for (int h = 0; h < 64; ++h)
        s = fmaf(qw2[j * 64 + h], kw2[jp * 64 + h], s);
    g_W[j * 32 + jp] = s;
    if (j == 0) {
        float su = 0.f;
        #pragma unroll
        for (int h = 0; h < 64; ++h)
            su = fmaf(qb2[h], kw2[jp * 64 + h], su);
        g_u[jp] = su;
    }
}

__global__ __launch_bounds__(THREADS, 2) void nearfield_kernel(
    const float* __restrict__ rss_t,          // [B,12]
    const float* __restrict__ led_features,   // [B,16,8]
    const float* __restrict__ led_positions,  // [B,16,3]
    const float* __restrict__ prev_pos,       // [B,3]
    const int*   __restrict__ freq_mask,      // [12,16]
    const float* __restrict__ gw1, const float* __restrict__ gb1,
    const float* __restrict__ gw2, const float* __restrict__ gb2,
    const float* __restrict__ qw1, const float* __restrict__ qb1,
    const float* __restrict__ kw1, const float* __restrict__ kb1,
    const float* __restrict__ sigma,
    float* __restrict__ out_attn,             // [B,12,16]
    float* __restrict__ out_iw)               // [B,12]
{
    __shared__ __align__(16) float s_kw1[11 * 32];
    __shared__ __align__(16) float s_kb1[32];
    __shared__ __align__(16) float s_W[32 * 32];
    __shared__ __align__(16) float s_u[32];
    __shared__ __align__(16) float s_qw1[32];
    __shared__ __align__(16) float s_qb1[32];
    __shared__ float s_gw1[16], s_gb1[16], s_gw2[16];
    __shared__ float s_gb2, s_scale;
    __shared__ unsigned s_mask[12];
    __shared__ __align__(16) float s_rk[NB * RKSTRIDE];
    __shared__ float s_dist[NB * 16];

    const int tid = threadIdx.x;

    // ---- cooperative weight staging ----
    for (int i = tid; i < 352; i += THREADS) s_kw1[i] = kw1[i];
    for (int i = tid; i < 1024; i += THREADS) s_W[i] = g_W[i];
    if (tid < 32) {
        s_kb1[tid] = kb1[tid];
        s_u[tid]   = g_u[tid];
        s_qw1[tid] = qw1[tid];
        s_qb1[tid] = qb1[tid];
    }
    if (tid < 16) {
        s_gw1[tid] = gw1[tid];
        s_gb1[tid] = gb1[tid];
        s_gw2[tid] = gw2[tid];
    }
    if (tid == 0) {
        float sg = sigma[0];
        s_gb2 = gb2[0];
        s_scale = 0.5f / (sg * sg);   // 1/(2 sigma^2)
    }
    if (tid < 12) {
        unsigned m = 0;
        #pragma unroll
        for (int l = 0; l < 16; ++l)
            if (freq_mask[tid * 16 + l] != 0) m |= (1u << l);
        s_mask[tid] = m;
    }
    __syncthreads();

    const int block0 = blockIdx.x * NB;
    const float scale = s_scale;

    // ---- Phase K: subtask (b, l, half): 16 cols of rk = relu(led_in@kw1+kb1) ----
    // 512 subtasks over 384 threads
    for (int st = tid; st < NB * 16 * 2; st += THREADS) {
        int half = st & 1;
        int st2 = st >> 1;
        int b = st2 >> 4, l = st2 & 15;
        int batch = block0 + b;
        float in[11];
        const float* lf = led_features + (size_t)(batch * 16 + l) * 8;
        float4 f0 = *(const float4*)(lf);
        float4 f1 = *(const float4*)(lf + 4);
        in[0] = f0.x; in[1] = f0.y; in[2] = f0.z; in[3] = f0.w;
        in[4] = f1.x; in[5] = f1.y; in[6] = f1.z; in[7] = f1.w;
        const float* lp = led_positions + (size_t)(batch * 16 + l) * 3;
        in[8] = lp[0]; in[9] = lp[1]; in[10] = lp[2];
        if (half == 0) {
            const float* pp = prev_pos + (size_t)batch * 3;
            float dx = pp[0] - in[8], dy = pp[1] - in[9], dz = pp[2] - in[10];
            s_dist[b * 16 + l] = (dx * dx + dy * dy + dz * dz) * scale;
        }

        int c0 = half * 16;  // column base
        float* dst = s_rk + b * RKSTRIDE + l * 32 + c0;
        #pragma unroll
        for (int j4 = 0; j4 < 4; ++j4) {
            float4 a = *(const float4*)(s_kb1 + c0 + j4 * 4);
            #pragma unroll
            for (int d = 0; d < 11; ++d) {
                float4 w = *(const float4*)(s_kw1 + d * 32 + c0 + j4 * 4);
                a.x = fmaf(in[d], w.x, a.x);
                a.y = fmaf(in[d], w.y, a.y);
                a.z = fmaf(in[d], w.z, a.z);
                a.w = fmaf(in[d], w.w, a.w);
            }
            float4 r4;
            r4.x = fmaxf(a.x, 0.f); r4.y = fmaxf(a.y, 0.f);
            r4.z = fmaxf(a.z, 0.f); r4.w = fmaxf(a.w, 0.f);
            *(float4*)(dst + j4 * 4) = r4;
        }
    }
    __syncthreads();

    // ---- Phase G: thread-pair per (batch, r); each half owns 16 G columns ----
    {
        int half = tid & 1;
        int p = tid >> 1;                 // 0..191
        int b = p / 12, r = p - b * 12;
        int batch = block0 + b;
        int c0 = half * 16;
        float rss = rss_t[batch * 12 + r];

        // intensity gate MLP + hard threshold (duplicated across halves)
        float gacc = s_gb2;
        #pragma unroll
        for (int k = 0; k < 16; ++k) {
            float h = fmaxf(fmaf(rss, s_gw1[k], s_gb1[k]), 0.f);
            gacc = fmaf(h, s_gw2[k], gacc);
        }
        float sig = __frcp_rn(1.f + __expf(-gacc));
        float iw = (rss > 0.5f) ? sig : 0.f;
        if (half == 0) out_iw[batch * 12 + r] = iw;
        float x = rss * iw;

        // G[0..15] = u[c0..c0+15] + relu(x*qw1 + qb1) @ W[:, c0..c0+15]
        float G[16];
        #pragma unroll
        for (int k4 = 0; k4 < 4; ++k4) {
            float4 u4 = *(const float4*)(s_u + c0 + k4 * 4);
            G[k4 * 4 + 0] = u4.x; G[k4 * 4 + 1] = u4.y;
            G[k4 * 4 + 2] = u4.z; G[k4 * 4 + 3] = u4.w;
        }
        #pragma unroll
        for (int j = 0; j < 32; ++j) {
            float rq = fmaxf(fmaf(x, s_qw1[j], s_qb1[j]), 0.f);
            const float* wrow = s_W + j * 32 + c0;
            #pragma unroll
            for (int k4 = 0; k4 < 4; ++k4) {
                float4 w = *(const float4*)(wrow + k4 * 4);
                G[k4 * 4 + 0] = fmaf(rq, w.x, G[k4 * 4 + 0]);
                G[k4 * 4 + 1] = fmaf(rq, w.y, G[k4 * 4 + 1]);
                G[k4 * 4 + 2] = fmaf(rq, w.z, G[k4 * 4 + 2]);
                G[k4 * 4 + 3] = fmaf(rq, w.w, G[k4 * 4 + 3]);
            }
        }

        // partial scores, then pairwise combine via shuffle
        float s[16];
        const float* rkb = s_rk + b * RKSTRIDE + c0;
        #pragma unroll
        for (int l = 0; l < 16; ++l) {
            float acc = half ? 0.f : -s_dist[b * 16 + l];
            const float* rkl = rkb + l * 32;
            #pragma unroll
            for (int k4 = 0; k4 < 4; ++k4) {
                float4 v = *(const float4*)(rkl + k4 * 4);
                acc = fmaf(G[k4 * 4 + 0], v.x, acc);
                acc = fmaf(G[k4 * 4 + 1], v.y, acc);
                acc = fmaf(G[k4 * 4 + 2], v.z, acc);
                acc = fmaf(G[k4 * 4 + 3], v.w, acc);
            }
            s[l] = acc;
        }
        #pragma unroll
        for (int l = 0; l < 16; ++l)
            s[l] += __shfl_xor_sync(0xffffffffu, s[l], 1);

        // masked softmax over l (both halves compute identically)
        unsigned m = s_mask[r];
        if (m == 0u) {
            #pragma unroll
            for (int l = 0; l < 16; ++l) s[l] = 1.f / 16.f;
        } else {
            float mx = -3.402823466e38f;
            #pragma unroll
            for (int l = 0; l < 16; ++l)
                if (m & (1u << l)) mx = fmaxf(mx, s[l]);
            float sum = 0.f;
            #pragma unroll
            for (int l = 0; l < 16; ++l) {
                float e = (m & (1u << l)) ? __expf(s[l] - mx) : 0.f;
                s[l] = e;
                sum += e;
            }
            float inv = __frcp_rn(sum);
            #pragma unroll
            for (int l = 0; l < 16; ++l) s[l] *= inv;
        }

        // each half writes its 8 outputs
        float* dst = out_attn + (size_t)(batch * 12 + r) * 16 + half * 8;
        #pragma unroll
        for (int l4 = 0; l4 < 2; ++l4) {
            int base = half * 8 + l4 * 4;
            float4 o;
            o.x = s[base + 0]; o.y = s[base + 1];
            o.z = s[base + 2]; o.w = s[base + 3];
            *(float4*)(dst + l4 * 4) = o;
        }
    }
}

extern "C" void kernel_launch(void* const* d_in, const int* in_sizes, int n_in,
                              void* d_out, int out_size) {
    const float* rss_t  = (const float*)d_in[0];
    const float* led_f  = (const float*)d_in[1];
    const float* led_p  = (const float*)d_in[2];
    const float* prevp  = (const float*)d_in[3];
    const int*   fmask  = (const int*)  d_in[4];
    const float* gw1    = (const float*)d_in[5];
    const float* gb1    = (const float*)d_in[6];
    const float* gw2    = (const float*)d_in[7];
    const float* gb2    = (const float*)d_in[8];
    const float* qw1    = (const float*)d_in[9];
    const float* qb1    = (const float*)d_in[10];
    const float* qw2    = (const float*)d_in[11];
    const float* qb2    = (const float*)d_in[12];
    const float* kw1    = (const float*)d_in[13];
    const float* kb1    = (const float*)d_in[14];
    const float* kw2    = (const float*)d_in[15];
    const float* kb2    = (const float*)d_in[16];
    const float* sigma  = (const float*)d_in[17];
    (void)kb2; (void)n_in; (void)out_size;

    int B = in_sizes[0] / 12;
    float* out = (float*)d_out;
    float* out_attn = out;                       // [B,12,16]
    float* out_iw   = out + (size_t)B * 192;     // [B,12]

    precompute_kernel<<<1, 1024>>>(qw2, qb2, kw2);
    nearfield_kernel<<<B / NB, THREADS>>>(
        rss_t, led_f, led_p, prevp, fmask,
        gw1, gb1, gw2, gb2, qw1, qb1, kw1, kb1, sigma,
        out_attn, out_iw);
}

// round 7
// speedup vs baseline: 1.5816x; 1.3333x over previous
#include <cuda_runtime.h>

#define NB 16          // batches per block
#define THREADS 384    // = NB * 12 * 2 (thread-pair per (batch,r))
#define RKSTRIDE 516   // 16*32 + 4 pad floats
#define TSTRIDE 36     // bucket-table row stride (bank spread)

__device__ float g_C[33 * TSTRIDE];   // C_k[c]: constant part of Ghat per bucket
__device__ float g_D[33 * TSTRIDE];   // D_k[c]: slope part of Ghat per bucket
__device__ float g_ts[32];            // sorted thresholds

__global__ __launch_bounds__(256, 1) void precompute_kernel(
        const float* __restrict__ qw1,
        const float* __restrict__ qb1,
        const float* __restrict__ qw2,
        const float* __restrict__ qb2,
        const float* __restrict__ kw2) {
    __shared__ float sW[32 * 32];
    __shared__ float su[32];
    __shared__ float th_raw[32];
    __shared__ float s_sgn[32];       // >0: pos-slope rule, <0: neg-slope rule
    __shared__ int   sidx[32];

    int t = threadIdx.x;              // 256 threads
    // W = qw2 @ kw2^T  (32x32), 1024 entries over 256 threads
    for (int e = t; e < 1024; e += 256) {
        int j = e >> 5, jp = e & 31;
        float s = 0.f;
        #pragma unroll
        for (int h = 0; h < 64; ++h)
            s = fmaf(qw2[j * 64 + h], kw2[jp * 64 + h], s);
        sW[e] = s;
    }
    if (t < 32) {
        int jp = t;
        float su_ = 0.f;
        #pragma unroll
        for (int h = 0; h < 64; ++h)
            su_ = fmaf(qb2[h], kw2[jp * 64 + h], su_);
        su[jp] = su_;
        // thresholds
        float w = qw1[jp], b = qb1[jp];
        float th, sg;
        if (w > 0.f)      { th = -b / w; sg = 1.f; }
        else if (w < 0.f) { th = -b / w; sg = -1.f; }
        else              { th = (b > 0.f) ? -1e30f : 1e30f; sg = 1.f; }
        th_raw[jp] = th;
        s_sgn[jp] = sg;
    }
    __syncthreads();
    if (t < 32) {
        // stable rank sort
        float mt = th_raw[t];
        int r = 0;
        #pragma unroll
        for (int i = 0; i < 32; ++i) {
            float o = th_raw[i];
            if (o < mt || (o == mt && i < t)) ++r;
        }
        sidx[r] = t;
        g_ts[r] = mt;
    }
    __syncthreads();
    // bucket tables: k in [0,33), c in [0,32)
    for (int task = t; task < 33 * 32; task += 256) {
        int k = task >> 5, c = task & 31;
        float C = su[c], D = 0.f;
        for (int i = 0; i < 32; ++i) {
            int o = sidx[i];
            bool pos = (s_sgn[o] > 0.f);
            bool active = pos ? (i < k) : (i >= k);
            if (active) {
                float wv = sW[o * 32 + c];
                C = fmaf(qb1[o], wv, C);
                D = fmaf(qw1[o], wv, D);
            }
        }
        g_C[k * TSTRIDE + c] = C;
        g_D[k * TSTRIDE + c] = D;
    }
}

__global__ __launch_bounds__(THREADS, 2) void nearfield_kernel(
    const float* __restrict__ rss_t,          // [B,12]
    const float* __restrict__ led_features,   // [B,16,8]
    const float* __restrict__ led_positions,  // [B,16,3]
    const float* __restrict__ prev_pos,       // [B,3]
    const int*   __restrict__ freq_mask,      // [12,16]
    const float* __restrict__ gw1, const float* __restrict__ gb1,
    const float* __restrict__ gw2, const float* __restrict__ gb2,
    const float* __restrict__ kw1, const float* __restrict__ kb1,
    const float* __restrict__ sigma,
    float* __restrict__ out_attn,             // [B,12,16]
    float* __restrict__ out_iw)               // [B,12]
{
    __shared__ __align__(16) float s_kw1[11 * 32];
    __shared__ __align__(16) float s_kb1[32];
    __shared__ __align__(16) float s_C[33 * TSTRIDE];
    __shared__ __align__(16) float s_D[33 * TSTRIDE];
    __shared__ __align__(16) float s_ts[32];
    __shared__ float s_gw1[16], s_gb1[16], s_gw2[16];
    __shared__ float s_gb2, s_scale;
    __shared__ unsigned s_mask[12];
    __shared__ __align__(16) float s_rk[NB * RKSTRIDE];
    __shared__ float s_dist[NB * 16];

    const int tid = threadIdx.x;

    // ---- cooperative staging ----
    for (int i = tid; i < 352; i += THREADS) s_kw1[i] = kw1[i];
    for (int i = tid; i < 33 * TSTRIDE; i += THREADS) {
        s_C[i] = g_C[i];
        s_D[i] = g_D[i];
    }
    if (tid < 32) {
        s_kb1[tid] = kb1[tid];
        s_ts[tid]  = g_ts[tid];
    }
    if (tid < 16) {
        s_gw1[tid] = gw1[tid];
        s_gb1[tid] = gb1[tid];
        s_gw2[tid] = gw2[tid];
    }
    if (tid == 0) {
        float sg = sigma[0];
        s_gb2 = gb2[0];
        s_scale = 0.5f / (sg * sg);   // 1/(2 sigma^2)
    }
    if (tid < 12) {
        unsigned m = 0;
        #pragma unroll
        for (int l = 0; l < 16; ++l)
            if (freq_mask[tid * 16 + l] != 0) m |= (1u << l);
        s_mask[tid] = m;
    }
    __syncthreads();

    const int block0 = blockIdx.x * NB;
    const float scale = s_scale;

    // ---- Phase K: subtask (b, l, half): 16 cols of rk = relu(led_in@kw1+kb1) ----
    for (int st = tid; st < NB * 16 * 2; st += THREADS) {
        int half = st & 1;
        int st2 = st >> 1;
        int b = st2 >> 4, l = st2 & 15;
        int batch = block0 + b;
        float in[11];
        const float* lf = led_features + (size_t)(batch * 16 + l) * 8;
        float4 f0 = *(const float4*)(lf);
        float4 f1 = *(const float4*)(lf + 4);
        in[0] = f0.x; in[1] = f0.y; in[2] = f0.z; in[3] = f0.w;
        in[4] = f1.x; in[5] = f1.y; in[6] = f1.z; in[7] = f1.w;
        const float* lp = led_positions + (size_t)(batch * 16 + l) * 3;
        in[8] = lp[0]; in[9] = lp[1]; in[10] = lp[2];
        if (half == 0) {
            const float* pp = prev_pos + (size_t)batch * 3;
            float dx = pp[0] - in[8], dy = pp[1] - in[9], dz = pp[2] - in[10];
            s_dist[b * 16 + l] = (dx * dx + dy * dy + dz * dz) * scale;
        }

        int c0 = half * 16;
        float* dst = s_rk + b * RKSTRIDE + l * 32 + c0;
        #pragma unroll
        for (int j4 = 0; j4 < 4; ++j4) {
            float4 a = *(const float4*)(s_kb1 + c0 + j4 * 4);
            #pragma unroll
            for (int d = 0; d < 11; ++d) {
                float4 w = *(const float4*)(s_kw1 + d * 32 + c0 + j4 * 4);
                a.x = fmaf(in[d], w.x, a.x);
                a.y = fmaf(in[d], w.y, a.y);
                a.z = fmaf(in[d], w.z, a.z);
                a.w = fmaf(in[d], w.w, a.w);
            }
            float4 r4;
            r4.x = fmaxf(a.x, 0.f); r4.y = fmaxf(a.y, 0.f);
            r4.z = fmaxf(a.z, 0.f); r4.w = fmaxf(a.w, 0.f);
            *(float4*)(dst + j4 * 4) = r4;
        }
    }
    __syncthreads();

    // ---- Phase G: thread-pair per (batch, r); each half owns 16 G columns ----
    {
        int half = tid & 1;
        int p = tid >> 1;                 // 0..191
        int b = p / 12, r = p - b * 12;
        int batch = block0 + b;
        int c0 = half * 16;
        float rss = rss_t[batch * 12 + r];

        // intensity gate MLP + hard threshold (duplicated across halves)
        float gacc = s_gb2;
        #pragma unroll
        for (int k = 0; k < 16; ++k) {
            float h = fmaxf(fmaf(rss, s_gw1[k], s_gb1[k]), 0.f);
            gacc = fmaf(h, s_gw2[k], gacc);
        }
        float sig = __frcp_rn(1.f + __expf(-gacc));
        float iw = (rss > 0.5f) ? sig : 0.f;
        if (half == 0) out_iw[batch * 12 + r] = iw;
        float x = rss * iw;

        // bucket index: k = #{ ts[i] <= x }
        int kb = 0;
        #pragma unroll
        for (int i4 = 0; i4 < 8; ++i4) {
            float4 tv = *(const float4*)(s_ts + i4 * 4);
            kb += (tv.x <= x) + (tv.y <= x) + (tv.z <= x) + (tv.w <= x);
        }

        // Ghat half = C_k + x * D_k
        float G[16];
        const float* Crow = s_C + kb * TSTRIDE + c0;
        const float* Drow = s_D + kb * TSTRIDE + c0;
        #pragma unroll
        for (int k4 = 0; k4 < 4; ++k4) {
            float4 c4 = *(const float4*)(Crow + k4 * 4);
            float4 d4 = *(const float4*)(Drow + k4 * 4);
            G[k4 * 4 + 0] = fmaf(x, d4.x, c4.x);
            G[k4 * 4 + 1] = fmaf(x, d4.y, c4.y);
            G[k4 * 4 + 2] = fmaf(x, d4.z, c4.z);
            G[k4 * 4 + 3] = fmaf(x, d4.w, c4.w);
        }

        // partial scores, then pairwise combine via shuffle
        float s[16];
        const float* rkb = s_rk + b * RKSTRIDE + c0;
        #pragma unroll
        for (int l = 0; l < 16; ++l) {
            float acc = half ? 0.f : -s_dist[b * 16 + l];
            const float* rkl = rkb + l * 32;
            #pragma unroll
            for (int k4 = 0; k4 < 4; ++k4) {
                float4 v = *(const float4*)(rkl + k4 * 4);
                acc = fmaf(G[k4 * 4 + 0], v.x, acc);
                acc = fmaf(G[k4 * 4 + 1], v.y, acc);
                acc = fmaf(G[k4 * 4 + 2], v.z, acc);
                acc = fmaf(G[k4 * 4 + 3], v.w, acc);
            }
            s[l] = acc;
        }
        #pragma unroll
        for (int l = 0; l < 16; ++l)
            s[l] += __shfl_xor_sync(0xffffffffu, s[l], 1);

        // masked softmax over l (both halves compute identically)
        unsigned m = s_mask[r];
        if (m == 0u) {
            #pragma unroll
            for (int l = 0; l < 16; ++l) s[l] = 1.f / 16.f;
        } else {
            float mx = -3.402823466e38f;
            #pragma unroll
            for (int l = 0; l < 16; ++l)
                if (m & (1u << l)) mx = fmaxf(mx, s[l]);
            float sum = 0.f;
            #pragma unroll
            for (int l = 0; l < 16; ++l) {
                float e = (m & (1u << l)) ? __expf(s[l] - mx) : 0.f;
                s[l] = e;
                sum += e;
            }
            float inv = __frcp_rn(sum);
            #pragma unroll
            for (int l = 0; l < 16; ++l) s[l] *= inv;
        }

        // each half writes its 8 outputs
        float* dst = out_attn + (size_t)(batch * 12 + r) * 16 + half * 8;
        #pragma unroll
        for (int l4 = 0; l4 < 2; ++l4) {
            int base = half * 8 + l4 * 4;
            float4 o;
            o.x = s[base + 0]; o.y = s[base + 1];
            o.z = s[base + 2]; o.w = s[base + 3];
            *(float4*)(dst + l4 * 4) = o;
        }
    }
}

extern "C" void kernel_launch(void* const* d_in, const int* in_sizes, int n_in,
                              void* d_out, int out_size) {
    const float* rss_t  = (const float*)d_in[0];
    const float* led_f  = (const float*)d_in[1];
    const float* led_p  = (const float*)d_in[2];
    const float* prevp  = (const float*)d_in[3];
    const int*   fmask  = (const int*)  d_in[4];
    const float* gw1    = (const float*)d_in[5];
    const float* gb1    = (const float*)d_in[6];
    const float* gw2    = (const float*)d_in[7];
    const float* gb2    = (const float*)d_in[8];
    const float* qw1    = (const float*)d_in[9];
    const float* qb1    = (const float*)d_in[10];
    const float* qw2    = (const float*)d_in[11];
    const float* qb2    = (const float*)d_in[12];
    const float* kw1    = (const float*)d_in[13];
    const float* kb1    = (const float*)d_in[14];
    const float* kw2    = (const float*)d_in[15];
    const float* kb2    = (const float*)d_in[16];
    const float* sigma  = (const float*)d_in[17];
    (void)kb2; (void)n_in; (void)out_size;

    int B = in_sizes[0] / 12;
    float* out = (float*)d_out;
    float* out_attn = out;                       // [B,12,16]
    float* out_iw   = out + (size_t)B * 192;     // [B,12]

    precompute_kernel<<<1, 256>>>(qw1, qb1, qw2, qb2, kw2);
    nearfield_kernel<<<B / NB, THREADS>>>(
        rss_t, led_f, led_p, prevp, fmask,
        gw1, gb1, gw2, gb2, kw1, kb1, sigma,
        out_attn, out_iw);
}